// round 6
// baseline (speedup 1.0000x reference)
#include <cuda_runtime.h>
#include <cuda_bf16.h>

#define EPS 1e-5f
#define LN3 1.0986122886681098f

// ---- static scratch: per-row softmax weights ----
__device__ __align__(16) float4 g_wt[1 << 19];

__device__ __forceinline__ float tanh_approx(float v) {
    float r;
    asm("tanh.approx.f32 %0, %1;" : "=f"(r) : "f"(v));
    return r;
}

__device__ __forceinline__ unsigned long long ffma2(
    unsigned long long a, unsigned long long b, unsigned long long c)
{
    unsigned long long d;
    asm("fma.rn.f32x2 %0, %1, %2, %3;" : "=l"(d) : "l"(a), "l"(b), "l"(c));
    return d;
}

// ================= Kernel 1: pure streaming (attention + pooled) =================
__global__ __launch_bounds__(256, 3) void stream_kernel(
    const float* __restrict__ x, const float* __restrict__ mask,
    const float* __restrict__ attn_w, const float* __restrict__ attn_b,
    float* __restrict__ out, int B, int write_weight)
{
    __shared__ float4 s_aw[64];
    __shared__ float s_ab;
    const int tid = threadIdx.x;
    for (int i = tid; i < 64; i += 256) s_aw[i] = ((const float4*)attn_w)[i];
    if (tid == 0) s_ab = attn_b[0];
    __syncthreads();

    const int lane = tid & 31;
    const unsigned FULL = 0xFFFFFFFFu;
    const float4 wa = s_aw[lane], wb = s_aw[32 + lane];
    const float ab = s_ab;

    const int gwarp = blockIdx.x * 8 + (tid >> 5);
    const int totW = gridDim.x * 8;

    for (long long b = gwarp; b < B; b += totW) {
        const float4 mk = __ldg(((const float4*)mask) + b);   // issued early
        const float4* xr = (const float4*)(x + b * 1024);
        float4 xa0 = xr[lane],       xb0 = xr[32 + lane];
        float4 xa1 = xr[64 + lane],  xb1 = xr[96 + lane];
        float4 xa2 = xr[128 + lane], xb2 = xr[160 + lane];
        float4 xa3 = xr[192 + lane], xb3 = xr[224 + lane];

        float s0 = xa0.x*wa.x + xa0.y*wa.y + xa0.z*wa.z + xa0.w*wa.w
                 + xb0.x*wb.x + xb0.y*wb.y + xb0.z*wb.z + xb0.w*wb.w;
        float s1 = xa1.x*wa.x + xa1.y*wa.y + xa1.z*wa.z + xa1.w*wa.w
                 + xb1.x*wb.x + xb1.y*wb.y + xb1.z*wb.z + xb1.w*wb.w;
        float s2 = xa2.x*wa.x + xa2.y*wa.y + xa2.z*wa.z + xa2.w*wa.w
                 + xb2.x*wb.x + xb2.y*wb.y + xb2.z*wb.z + xb2.w*wb.w;
        float s3 = xa3.x*wa.x + xa3.y*wa.y + xa3.z*wa.z + xa3.w*wa.w
                 + xb3.x*wb.x + xb3.y*wb.y + xb3.z*wb.z + xb3.w*wb.w;
        #pragma unroll
        for (int o = 16; o; o >>= 1) {
            s0 += __shfl_xor_sync(FULL, s0, o);
            s1 += __shfl_xor_sync(FULL, s1, o);
            s2 += __shfl_xor_sync(FULL, s2, o);
            s3 += __shfl_xor_sync(FULL, s3, o);
        }

        float t0 = tanh_approx(s0 + ab) + mk.x;
        float t1 = tanh_approx(s1 + ab) + mk.y;
        float t2 = tanh_approx(s2 + ab) + mk.z;
        float t3 = tanh_approx(s3 + ab) + mk.w;

        float mx = fmaxf(fmaxf(t0, t1), fmaxf(t2, t3));
        float e0 = __expf(t0 - mx), e1 = __expf(t1 - mx);
        float e2 = __expf(t2 - mx), e3 = __expf(t3 - mx);
        float inv = 1.0f / (e0 + e1 + e2 + e3);
        float wt0 = e0 * inv, wt1 = e1 * inv, wt2 = e2 * inv, wt3 = e3 * inv;

        float4 pa, pb;
        pa.x = wt0*xa0.x + wt1*xa1.x + wt2*xa2.x + wt3*xa3.x;
        pa.y = wt0*xa0.y + wt1*xa1.y + wt2*xa2.y + wt3*xa3.y;
        pa.z = wt0*xa0.z + wt1*xa1.z + wt2*xa2.z + wt3*xa3.z;
        pa.w = wt0*xa0.w + wt1*xa1.w + wt2*xa2.w + wt3*xa3.w;
        pb.x = wt0*xb0.x + wt1*xb1.x + wt2*xb2.x + wt3*xb3.x;
        pb.y = wt0*xb0.y + wt1*xb1.y + wt2*xb2.y + wt3*xb3.y;
        pb.z = wt0*xb0.z + wt1*xb1.z + wt2*xb2.z + wt3*xb3.z;
        pb.w = wt0*xb0.w + wt1*xb1.w + wt2*xb2.w + wt3*xb3.w;

        float4* orow = (float4*)(out + (size_t)b * 256);
        orow[lane]      = pa;
        orow[32 + lane] = pb;

        if (lane == 0) {
            float4 wv = make_float4(wt0, wt1, wt2, wt3);
            g_wt[b] = wv;
            if (write_weight)
                *(float4*)(out + (size_t)B * 256 + (size_t)b * 4) = wv;
        }
    }
}

// ====== Kernel 2: classifier MLP (constants folded in-block) + rare gather ======
__global__ __launch_bounds__(256) void mlp_kernel(
    const float* __restrict__ x,
    const float* __restrict__ w1, const float* __restrict__ b1,
    const float* __restrict__ g1, const float* __restrict__ be1,
    const float* __restrict__ m1, const float* __restrict__ v1,
    const float* __restrict__ w2, const float* __restrict__ b2,
    const float* __restrict__ g2, const float* __restrict__ be2,
    const float* __restrict__ m2, const float* __restrict__ v2,
    const float* __restrict__ w3, const float* __restrict__ b3,
    float* __restrict__ out, int B, int write_cls)
{
    __shared__ float4 s_M4[128 * 16];   // 32KB: k-major M[k*64+j] = w2[j][k]*a1[k]
    __shared__ float4 s_w1p[128];       // [k] = w1 row k
    __shared__ float  s_b1[128];
    __shared__ float  s_q[64], s_e[64], s_ct[64];
    __shared__ float  s_a1[128], s_c1[128];
    __shared__ float  s_C;

    const int tid = threadIdx.x;

    // ---- block init: fold all classifier constants from raw inputs ----
    for (int i = tid; i < 128; i += 256) {
        float a = g1[i] * rsqrtf(v1[i] + EPS);
        s_a1[i] = a; s_c1[i] = be1[i] - a * m1[i]; s_b1[i] = b1[i];
        s_w1p[i] = make_float4(w1[i*4], w1[i*4+1], w1[i*4+2], w1[i*4+3]);
    }
    __syncthreads();

    float* s_M = (float*)s_M4;
    for (int i = tid; i < 8192; i += 256) {
        int j = i >> 7, k = i & 127;
        s_M[k * 64 + j] = w2[j * 128 + k] * s_a1[k];
    }
    if (tid < 64) {
        float acc = b2[tid];
        #pragma unroll 8
        for (int k = 0; k < 128; k++) acc += w2[tid * 128 + k] * s_c1[k];
        s_q[tid] = acc;
        float a2 = g2[tid] * rsqrtf(v2[tid] + EPS);
        float wd = w3[64 + tid] - w3[tid];
        s_e[tid] = wd * a2;
        s_ct[tid] = wd * (be2[tid] - a2 * m2[tid]);
    }
    __syncthreads();
    if (tid == 0) {
        float C = b3[1] - b3[0];
        #pragma unroll 8
        for (int j = 0; j < 64; j++) C += s_ct[j];
        s_C = C;
    }
    __syncthreads();

    const int lane = tid & 31;
    const unsigned FULL = 0xFFFFFFFFu;
    const float Cc = s_C;
    const int nGroups = (B + 31) >> 5;
    const int gwarp = blockIdx.x * 8 + (tid >> 5);
    const int totW = gridDim.x * 8;

    for (int g = gwarp; g < nGroups; g += totW) {
        const long long base = (long long)g << 5;
        const int rmax = (int)min((long long)32, (long long)B - base);
        const bool myvalid = (lane < rmax);

        float4 wt = myvalid ? g_wt[base + lane] : make_float4(1.f, 0.f, 0.f, 0.f);

        // argmax of stored weights (== reference argmax(weight), first occurrence)
        int mmi = 0; float bm = wt.x;
        if (wt.y > bm) { bm = wt.y; mmi = 1; }
        if (wt.z > bm) { bm = wt.z; mmi = 2; }
        if (wt.w > bm) { bm = wt.w; mmi = 3; }

        // single-pass layer1+layer2: 32 independent f32x2 accumulators
        unsigned long long acc[32];
        #pragma unroll
        for (int i = 0; i < 32; i++) acc[i] = 0ull;

        #pragma unroll 2
        for (int k = 0; k < 128; k++) {
            float4 wp = s_w1p[k];
            float z = fmaf(wt.x, wp.x, fmaf(wt.y, wp.y,
                      fmaf(wt.z, wp.z, fmaf(wt.w, wp.w, s_b1[k]))));
            float v = fmaxf(z, 0.0f);
            unsigned long long vv;
            asm("mov.b64 %0, {%1, %1};" : "=l"(vv) : "f"(v));
            const ulonglong2* row = (const ulonglong2*)s_M4 + k * 16;
            #pragma unroll
            for (int t = 0; t < 16; t++) {
                ulonglong2 m = row[t];
                acc[2 * t]     = ffma2(m.x, vv, acc[2 * t]);
                acc[2 * t + 1] = ffma2(m.y, vv, acc[2 * t + 1]);
            }
        }

        float dec = Cc;
        #pragma unroll
        for (int i = 0; i < 32; i++) {
            float z0 = __uint_as_float((unsigned)(acc[i] & 0xFFFFFFFFull)) + s_q[2 * i];
            float z1 = __uint_as_float((unsigned)(acc[i] >> 32))           + s_q[2 * i + 1];
            dec = fmaf(s_e[2 * i],     fmaxf(z0, 0.0f), dec);
            dec = fmaf(s_e[2 * i + 1], fmaxf(z1, 0.0f), dec);
        }
        const bool cls1 = myvalid && (dec > LN3);

        // rare overwrite with argmax-gathered member
        unsigned mbits = __ballot_sync(FULL, cls1);
        while (mbits) {
            const int r = __ffs(mbits) - 1;
            mbits &= mbits - 1;
            const long long b = base + r;
            const int gmi = __shfl_sync(FULL, mmi, r);
            const float4* gsrc = (const float4*)(x + b * 1024 + (size_t)gmi * 256);
            float4 v0 = gsrc[lane], v1 = gsrc[32 + lane];
            float4* orow = (float4*)(out + (size_t)b * 256);
            orow[lane]      = v0;
            orow[32 + lane] = v1;
        }
        if (write_cls && myvalid)
            out[(size_t)B * 260 + base + lane] = cls1 ? 1.0f : 0.0f;
    }
}

extern "C" void kernel_launch(void* const* d_in, const int* in_sizes, int n_in,
                              void* d_out, int out_size)
{
    const float* x      = (const float*)d_in[0];
    const float* mask   = (const float*)d_in[1];
    const float* attn_w = (const float*)d_in[2];
    const float* attn_b = (const float*)d_in[3];
    const float* w1     = (const float*)d_in[4];
    const float* b1     = (const float*)d_in[5];
    const float* g1     = (const float*)d_in[6];
    const float* be1    = (const float*)d_in[7];
    const float* m1     = (const float*)d_in[8];
    const float* v1     = (const float*)d_in[9];
    const float* w2     = (const float*)d_in[10];
    const float* b2     = (const float*)d_in[11];
    const float* g2     = (const float*)d_in[12];
    const float* be2    = (const float*)d_in[13];
    const float* m2     = (const float*)d_in[14];
    const float* v2     = (const float*)d_in[15];
    const float* w3     = (const float*)d_in[16];
    const float* b3     = (const float*)d_in[17];
    float* out = (float*)d_out;

    const int B = in_sizes[0] / 1024;   // x = [B,4,256]
    const long long need_w = (long long)B * 260;
    const long long need_c = (long long)B * 261;
    const int write_weight = ((long long)out_size >= need_w) ? 1 : 0;
    const int write_cls    = ((long long)out_size >= need_c) ? 1 : 0;

    stream_kernel<<<2048, 256>>>(x, mask, attn_w, attn_b, out, B, write_weight);
    mlp_kernel<<<2048, 256>>>(x, w1, b1, g1, be1, m1, v1,
                              w2, b2, g2, be2, m2, v2, w3, b3,
                              out, B, write_cls);
}

// round 7
// speedup vs baseline: 1.1549x; 1.1549x over previous
#include <cuda_runtime.h>
#include <cuda_bf16.h>

#define EPS 1e-5f
#define LN3 1.0986122886681098f

// ---- static scratch: per-row softmax weights ----
__device__ __align__(16) float4 g_wt[1 << 19];

__device__ __forceinline__ float tanh_approx(float v) {
    float r;
    asm("tanh.approx.f32 %0, %1;" : "=f"(r) : "f"(v));
    return r;
}

__device__ __forceinline__ unsigned long long ffma2(
    unsigned long long a, unsigned long long b, unsigned long long c)
{
    unsigned long long d;
    asm("fma.rn.f32x2 %0, %1, %2, %3;" : "=l"(d) : "l"(a), "l"(b), "l"(c));
    return d;
}

// ================= Kernel 1: pure streaming (attention + pooled) =================
// ~190us measured, ~7TB/s effective -- at the HBM roofline. Do not touch.
__global__ __launch_bounds__(256, 3) void stream_kernel(
    const float* __restrict__ x, const float* __restrict__ mask,
    const float* __restrict__ attn_w, const float* __restrict__ attn_b,
    float* __restrict__ out, int B, int write_weight)
{
    __shared__ float4 s_aw[64];
    __shared__ float s_ab;
    const int tid = threadIdx.x;
    for (int i = tid; i < 64; i += 256) s_aw[i] = ((const float4*)attn_w)[i];
    if (tid == 0) s_ab = attn_b[0];
    __syncthreads();

    const int lane = tid & 31;
    const unsigned FULL = 0xFFFFFFFFu;
    const float4 wa = s_aw[lane], wb = s_aw[32 + lane];
    const float ab = s_ab;

    const int gwarp = blockIdx.x * 8 + (tid >> 5);
    const int totW = gridDim.x * 8;

    for (long long b = gwarp; b < B; b += totW) {
        const float4 mk = __ldg(((const float4*)mask) + b);   // issued early
        const float4* xr = (const float4*)(x + b * 1024);
        float4 xa0 = xr[lane],       xb0 = xr[32 + lane];
        float4 xa1 = xr[64 + lane],  xb1 = xr[96 + lane];
        float4 xa2 = xr[128 + lane], xb2 = xr[160 + lane];
        float4 xa3 = xr[192 + lane], xb3 = xr[224 + lane];

        float s0 = xa0.x*wa.x + xa0.y*wa.y + xa0.z*wa.z + xa0.w*wa.w
                 + xb0.x*wb.x + xb0.y*wb.y + xb0.z*wb.z + xb0.w*wb.w;
        float s1 = xa1.x*wa.x + xa1.y*wa.y + xa1.z*wa.z + xa1.w*wa.w
                 + xb1.x*wb.x + xb1.y*wb.y + xb1.z*wb.z + xb1.w*wb.w;
        float s2 = xa2.x*wa.x + xa2.y*wa.y + xa2.z*wa.z + xa2.w*wa.w
                 + xb2.x*wb.x + xb2.y*wb.y + xb2.z*wb.z + xb2.w*wb.w;
        float s3 = xa3.x*wa.x + xa3.y*wa.y + xa3.z*wa.z + xa3.w*wa.w
                 + xb3.x*wb.x + xb3.y*wb.y + xb3.z*wb.z + xb3.w*wb.w;
        #pragma unroll
        for (int o = 16; o; o >>= 1) {
            s0 += __shfl_xor_sync(FULL, s0, o);
            s1 += __shfl_xor_sync(FULL, s1, o);
            s2 += __shfl_xor_sync(FULL, s2, o);
            s3 += __shfl_xor_sync(FULL, s3, o);
        }

        float t0 = tanh_approx(s0 + ab) + mk.x;
        float t1 = tanh_approx(s1 + ab) + mk.y;
        float t2 = tanh_approx(s2 + ab) + mk.z;
        float t3 = tanh_approx(s3 + ab) + mk.w;

        float mx = fmaxf(fmaxf(t0, t1), fmaxf(t2, t3));
        float e0 = __expf(t0 - mx), e1 = __expf(t1 - mx);
        float e2 = __expf(t2 - mx), e3 = __expf(t3 - mx);
        float inv = 1.0f / (e0 + e1 + e2 + e3);
        float wt0 = e0 * inv, wt1 = e1 * inv, wt2 = e2 * inv, wt3 = e3 * inv;

        float4 pa, pb;
        pa.x = wt0*xa0.x + wt1*xa1.x + wt2*xa2.x + wt3*xa3.x;
        pa.y = wt0*xa0.y + wt1*xa1.y + wt2*xa2.y + wt3*xa3.y;
        pa.z = wt0*xa0.z + wt1*xa1.z + wt2*xa2.z + wt3*xa3.z;
        pa.w = wt0*xa0.w + wt1*xa1.w + wt2*xa2.w + wt3*xa3.w;
        pb.x = wt0*xb0.x + wt1*xb1.x + wt2*xb2.x + wt3*xb3.x;
        pb.y = wt0*xb0.y + wt1*xb1.y + wt2*xb2.y + wt3*xb3.y;
        pb.z = wt0*xb0.z + wt1*xb1.z + wt2*xb2.z + wt3*xb3.z;
        pb.w = wt0*xb0.w + wt1*xb1.w + wt2*xb2.w + wt3*xb3.w;

        float4* orow = (float4*)(out + (size_t)b * 256);
        orow[lane]      = pa;
        orow[32 + lane] = pb;

        if (lane == 0) {
            float4 wv = make_float4(wt0, wt1, wt2, wt3);
            g_wt[b] = wv;
            if (write_weight)
                *(float4*)(out + (size_t)B * 256 + (size_t)b * 4) = wv;
        }
    }
}

// ====== Kernel 2: classifier MLP, chunked accumulators (reg-capped) ======
__global__ __launch_bounds__(256, 3) void mlp_kernel(
    const float* __restrict__ x,
    const float* __restrict__ w1, const float* __restrict__ b1,
    const float* __restrict__ g1, const float* __restrict__ be1,
    const float* __restrict__ m1, const float* __restrict__ v1,
    const float* __restrict__ w2, const float* __restrict__ b2,
    const float* __restrict__ g2, const float* __restrict__ be2,
    const float* __restrict__ m2, const float* __restrict__ v2,
    const float* __restrict__ w3, const float* __restrict__ b3,
    float* __restrict__ out, int B, int write_cls)
{
    __shared__ float4 s_M4[128 * 16];   // 32KB: k-major M[k*64+j] = w2[j][k]*a1[k]
    __shared__ float4 s_w1p[128];       // [k] = w1 row k
    __shared__ float  s_b1[128];
    __shared__ float  s_q[64], s_e[64], s_ct[64];
    __shared__ float  s_a1[128], s_c1[128];
    __shared__ float  s_C;

    const int tid = threadIdx.x;

    // ---- block init: fold all classifier constants from raw inputs ----
    for (int i = tid; i < 128; i += 256) {
        float a = g1[i] * rsqrtf(v1[i] + EPS);
        s_a1[i] = a; s_c1[i] = be1[i] - a * m1[i]; s_b1[i] = b1[i];
        s_w1p[i] = make_float4(w1[i*4], w1[i*4+1], w1[i*4+2], w1[i*4+3]);
    }
    __syncthreads();

    float* s_M = (float*)s_M4;
    for (int i = tid; i < 8192; i += 256) {
        int j = i >> 7, k = i & 127;
        s_M[k * 64 + j] = w2[j * 128 + k] * s_a1[k];
    }
    if (tid < 64) {
        float acc = b2[tid];
        #pragma unroll 8
        for (int k = 0; k < 128; k++) acc += w2[tid * 128 + k] * s_c1[k];
        s_q[tid] = acc;
        float a2 = g2[tid] * rsqrtf(v2[tid] + EPS);
        float wd = w3[64 + tid] - w3[tid];
        s_e[tid] = wd * a2;
        s_ct[tid] = wd * (be2[tid] - a2 * m2[tid]);
    }
    __syncthreads();
    if (tid == 0) {
        float C = b3[1] - b3[0];
        #pragma unroll 8
        for (int j = 0; j < 64; j++) C += s_ct[j];
        s_C = C;
    }
    __syncthreads();

    const int lane = tid & 31;
    const unsigned FULL = 0xFFFFFFFFu;
    const float Cc = s_C;
    const int nGroups = (B + 31) >> 5;
    const int gwarp = blockIdx.x * 8 + (tid >> 5);
    const int totW = gridDim.x * 8;

    for (int g = gwarp; g < nGroups; g += totW) {
        const long long base = (long long)g << 5;
        const int rmax = (int)min((long long)32, (long long)B - base);
        const bool myvalid = (lane < rmax);

        float4 wt = myvalid ? g_wt[base + lane] : make_float4(1.f, 0.f, 0.f, 0.f);

        // argmax of stored weights (== reference argmax(weight), first occurrence)
        int mmi = 0; float bm = wt.x;
        if (wt.y > bm) { bm = wt.y; mmi = 1; }
        if (wt.z > bm) { bm = wt.z; mmi = 2; }
        if (wt.w > bm) { bm = wt.w; mmi = 3; }

        // layer1+layer2 in 2 j-chunks of 32 outputs (acc = 16 u64 = 32 regs)
        float dec = Cc;
        #pragma unroll
        for (int c = 0; c < 2; c++) {
            unsigned long long acc[16];
            #pragma unroll
            for (int i = 0; i < 16; i++) acc[i] = 0ull;

            #pragma unroll 4
            for (int k = 0; k < 128; k++) {
                float4 wp = s_w1p[k];
                float z = fmaf(wt.x, wp.x, fmaf(wt.y, wp.y,
                          fmaf(wt.z, wp.z, fmaf(wt.w, wp.w, s_b1[k]))));
                float v = fmaxf(z, 0.0f);
                unsigned long long vv;
                asm("mov.b64 %0, {%1, %1};" : "=l"(vv) : "f"(v));
                const ulonglong2* row = (const ulonglong2*)s_M4 + k * 16 + c * 8;
                #pragma unroll
                for (int t = 0; t < 8; t++) {
                    ulonglong2 m = row[t];
                    acc[2 * t]     = ffma2(m.x, vv, acc[2 * t]);
                    acc[2 * t + 1] = ffma2(m.y, vv, acc[2 * t + 1]);
                }
            }
            #pragma unroll
            for (int i = 0; i < 16; i++) {
                float z0 = __uint_as_float((unsigned)(acc[i] & 0xFFFFFFFFull)) + s_q[c * 32 + 2 * i];
                float z1 = __uint_as_float((unsigned)(acc[i] >> 32))           + s_q[c * 32 + 2 * i + 1];
                dec = fmaf(s_e[c * 32 + 2 * i],     fmaxf(z0, 0.0f), dec);
                dec = fmaf(s_e[c * 32 + 2 * i + 1], fmaxf(z1, 0.0f), dec);
            }
        }
        const bool cls1 = myvalid && (dec > LN3);

        // rare overwrite with argmax-gathered member
        unsigned mbits = __ballot_sync(FULL, cls1);
        while (mbits) {
            const int r = __ffs(mbits) - 1;
            mbits &= mbits - 1;
            const long long b = base + r;
            const int gmi = __shfl_sync(FULL, mmi, r);
            const float4* gsrc = (const float4*)(x + b * 1024 + (size_t)gmi * 256);
            float4 v0 = gsrc[lane], v1 = gsrc[32 + lane];
            float4* orow = (float4*)(out + (size_t)b * 256);
            orow[lane]      = v0;
            orow[32 + lane] = v1;
        }
        if (write_cls && myvalid)
            out[(size_t)B * 260 + base + lane] = cls1 ? 1.0f : 0.0f;
    }
}

extern "C" void kernel_launch(void* const* d_in, const int* in_sizes, int n_in,
                              void* d_out, int out_size)
{
    const float* x      = (const float*)d_in[0];
    const float* mask   = (const float*)d_in[1];
    const float* attn_w = (const float*)d_in[2];
    const float* attn_b = (const float*)d_in[3];
    const float* w1     = (const float*)d_in[4];
    const float* b1     = (const float*)d_in[5];
    const float* g1     = (const float*)d_in[6];
    const float* be1    = (const float*)d_in[7];
    const float* m1     = (const float*)d_in[8];
    const float* v1     = (const float*)d_in[9];
    const float* w2     = (const float*)d_in[10];
    const float* b2     = (const float*)d_in[11];
    const float* g2     = (const float*)d_in[12];
    const float* be2    = (const float*)d_in[13];
    const float* m2     = (const float*)d_in[14];
    const float* v2     = (const float*)d_in[15];
    const float* w3     = (const float*)d_in[16];
    const float* b3     = (const float*)d_in[17];
    float* out = (float*)d_out;

    const int B = in_sizes[0] / 1024;   // x = [B,4,256]
    const long long need_w = (long long)B * 260;
    const long long need_c = (long long)B * 261;
    const int write_weight = ((long long)out_size >= need_w) ? 1 : 0;
    const int write_cls    = ((long long)out_size >= need_c) ? 1 : 0;

    stream_kernel<<<2048, 256>>>(x, mask, attn_w, attn_b, out, B, write_weight);
    mlp_kernel<<<1024, 256>>>(x, w1, b1, g1, be1, m1, v1,
                              w2, b2, g2, be2, m2, v2, w3, b3,
                              out, B, write_cls);
}

// round 8
// speedup vs baseline: 1.2900x; 1.1169x over previous
#include <cuda_runtime.h>
#include <cuda_bf16.h>

#define EPS 1e-5f
#define LN3 1.0986122886681098f

// ---- static scratch: per-row softmax weights ----
__device__ __align__(16) float4 g_wt[1 << 19];

__device__ __forceinline__ float tanh_approx(float v) {
    float r;
    asm("tanh.approx.f32 %0, %1;" : "=f"(r) : "f"(v));
    return r;
}

__device__ __forceinline__ unsigned long long ffma2(
    unsigned long long a, unsigned long long b, unsigned long long c)
{
    unsigned long long d;
    asm("fma.rn.f32x2 %0, %1, %2, %3;" : "=l"(d) : "l"(a), "l"(b), "l"(c));
    return d;
}

// ================= Kernel 1: pure streaming (attention + pooled) =================
// ~190us measured, ~7TB/s effective -- at the HBM roofline. Frozen.
__global__ __launch_bounds__(256, 3) void stream_kernel(
    const float* __restrict__ x, const float* __restrict__ mask,
    const float* __restrict__ attn_w, const float* __restrict__ attn_b,
    float* __restrict__ out, int B, int write_weight)
{
    __shared__ float4 s_aw[64];
    __shared__ float s_ab;
    const int tid = threadIdx.x;
    for (int i = tid; i < 64; i += 256) s_aw[i] = ((const float4*)attn_w)[i];
    if (tid == 0) s_ab = attn_b[0];
    __syncthreads();

    const int lane = tid & 31;
    const unsigned FULL = 0xFFFFFFFFu;
    const float4 wa = s_aw[lane], wb = s_aw[32 + lane];
    const float ab = s_ab;

    const int gwarp = blockIdx.x * 8 + (tid >> 5);
    const int totW = gridDim.x * 8;

    for (long long b = gwarp; b < B; b += totW) {
        const float4 mk = __ldg(((const float4*)mask) + b);   // issued early
        const float4* xr = (const float4*)(x + b * 1024);
        float4 xa0 = xr[lane],       xb0 = xr[32 + lane];
        float4 xa1 = xr[64 + lane],  xb1 = xr[96 + lane];
        float4 xa2 = xr[128 + lane], xb2 = xr[160 + lane];
        float4 xa3 = xr[192 + lane], xb3 = xr[224 + lane];

        float s0 = xa0.x*wa.x + xa0.y*wa.y + xa0.z*wa.z + xa0.w*wa.w
                 + xb0.x*wb.x + xb0.y*wb.y + xb0.z*wb.z + xb0.w*wb.w;
        float s1 = xa1.x*wa.x + xa1.y*wa.y + xa1.z*wa.z + xa1.w*wa.w
                 + xb1.x*wb.x + xb1.y*wb.y + xb1.z*wb.z + xb1.w*wb.w;
        float s2 = xa2.x*wa.x + xa2.y*wa.y + xa2.z*wa.z + xa2.w*wa.w
                 + xb2.x*wb.x + xb2.y*wb.y + xb2.z*wb.z + xb2.w*wb.w;
        float s3 = xa3.x*wa.x + xa3.y*wa.y + xa3.z*wa.z + xa3.w*wa.w
                 + xb3.x*wb.x + xb3.y*wb.y + xb3.z*wb.z + xb3.w*wb.w;
        #pragma unroll
        for (int o = 16; o; o >>= 1) {
            s0 += __shfl_xor_sync(FULL, s0, o);
            s1 += __shfl_xor_sync(FULL, s1, o);
            s2 += __shfl_xor_sync(FULL, s2, o);
            s3 += __shfl_xor_sync(FULL, s3, o);
        }

        float t0 = tanh_approx(s0 + ab) + mk.x;
        float t1 = tanh_approx(s1 + ab) + mk.y;
        float t2 = tanh_approx(s2 + ab) + mk.z;
        float t3 = tanh_approx(s3 + ab) + mk.w;

        float mx = fmaxf(fmaxf(t0, t1), fmaxf(t2, t3));
        float e0 = __expf(t0 - mx), e1 = __expf(t1 - mx);
        float e2 = __expf(t2 - mx), e3 = __expf(t3 - mx);
        float inv = 1.0f / (e0 + e1 + e2 + e3);
        float wt0 = e0 * inv, wt1 = e1 * inv, wt2 = e2 * inv, wt3 = e3 * inv;

        float4 pa, pb;
        pa.x = wt0*xa0.x + wt1*xa1.x + wt2*xa2.x + wt3*xa3.x;
        pa.y = wt0*xa0.y + wt1*xa1.y + wt2*xa2.y + wt3*xa3.y;
        pa.z = wt0*xa0.z + wt1*xa1.z + wt2*xa2.z + wt3*xa3.z;
        pa.w = wt0*xa0.w + wt1*xa1.w + wt2*xa2.w + wt3*xa3.w;
        pb.x = wt0*xb0.x + wt1*xb1.x + wt2*xb2.x + wt3*xb3.x;
        pb.y = wt0*xb0.y + wt1*xb1.y + wt2*xb2.y + wt3*xb3.y;
        pb.z = wt0*xb0.z + wt1*xb1.z + wt2*xb2.z + wt3*xb3.z;
        pb.w = wt0*xb0.w + wt1*xb1.w + wt2*xb2.w + wt3*xb3.w;

        float4* orow = (float4*)(out + (size_t)b * 256);
        orow[lane]      = pa;
        orow[32 + lane] = pb;

        if (lane == 0) {
            float4 wv = make_float4(wt0, wt1, wt2, wt3);
            g_wt[b] = wv;
            if (write_weight)
                *(float4*)(out + (size_t)B * 256 + (size_t)b * 4) = wv;
        }
    }
}

// ====== Kernel 2: classifier MLP, 4-row register blocking x 4 j-chunks ======
// One M traversal per warp serves 128 rows (LDS/row: 64 -> 16).
__global__ __launch_bounds__(128, 4) void mlp_kernel(
    const float* __restrict__ x,
    const float* __restrict__ w1, const float* __restrict__ b1,
    const float* __restrict__ g1, const float* __restrict__ be1,
    const float* __restrict__ m1, const float* __restrict__ v1,
    const float* __restrict__ w2, const float* __restrict__ b2,
    const float* __restrict__ g2, const float* __restrict__ be2,
    const float* __restrict__ m2, const float* __restrict__ v2,
    const float* __restrict__ w3, const float* __restrict__ b3,
    float* __restrict__ out, int B, int write_cls)
{
    __shared__ float4 s_M4[128 * 16];   // 32KB: k-major M[k*64+j] = w2[j][k]*a1[k]
    __shared__ float4 s_w1p[128];       // [k] = w1 row k
    __shared__ float  s_b1[128];
    __shared__ float  s_q[64], s_e[64], s_ct[64];
    __shared__ float  s_a1[128], s_c1[128];
    __shared__ float  s_C;

    const int tid = threadIdx.x;      // 128 threads

    // ---- block init: fold all classifier constants from raw inputs ----
    {
        float a = g1[tid] * rsqrtf(v1[tid] + EPS);
        s_a1[tid] = a; s_c1[tid] = be1[tid] - a * m1[tid]; s_b1[tid] = b1[tid];
        s_w1p[tid] = make_float4(w1[tid*4], w1[tid*4+1], w1[tid*4+2], w1[tid*4+3]);
    }
    __syncthreads();

    float* s_M = (float*)s_M4;
    for (int i = tid; i < 8192; i += 128) {
        int j = i >> 7, k = i & 127;
        s_M[k * 64 + j] = w2[j * 128 + k] * s_a1[k];
    }
    if (tid < 64) {
        float acc = b2[tid];
        #pragma unroll 8
        for (int k = 0; k < 128; k++) acc += w2[tid * 128 + k] * s_c1[k];
        s_q[tid] = acc;
        float a2 = g2[tid] * rsqrtf(v2[tid] + EPS);
        float wd = w3[64 + tid] - w3[tid];
        s_e[tid] = wd * a2;
        s_ct[tid] = wd * (be2[tid] - a2 * m2[tid]);
    }
    __syncthreads();
    if (tid == 0) {
        float C = b3[1] - b3[0];
        #pragma unroll 8
        for (int j = 0; j < 64; j++) C += s_ct[j];
        s_C = C;
    }
    __syncthreads();

    const int lane = tid & 31;
    const unsigned FULL = 0xFFFFFFFFu;
    const float Cc = s_C;
    const int nG = (B + 127) >> 7;          // 128-row groups
    const int wid = blockIdx.x * 4 + (tid >> 5);

    for (int g = wid; g < nG; g += gridDim.x * 4) {
        const long long base = (long long)g << 7;

        bool  valid[4];
        float4 wt[4];
        int   mmi[4];
        #pragma unroll
        for (int r = 0; r < 4; r++) {
            long long row = base + 32 * r + lane;
            valid[r] = (row < B);
            wt[r] = valid[r] ? g_wt[row] : make_float4(1.f, 0.f, 0.f, 0.f);
            int mi = 0; float bm = wt[r].x;
            if (wt[r].y > bm) { bm = wt[r].y; mi = 1; }
            if (wt[r].z > bm) { bm = wt[r].z; mi = 2; }
            if (wt[r].w > bm) { bm = wt[r].w; mi = 3; }
            mmi[r] = mi;
        }

        float dec[4] = {Cc, Cc, Cc, Cc};

        #pragma unroll
        for (int c = 0; c < 4; c++) {         // j-chunks of 16 outputs
            unsigned long long acc[4][8];
            #pragma unroll
            for (int r = 0; r < 4; r++)
                #pragma unroll
                for (int p = 0; p < 8; p++) acc[r][p] = 0ull;

            #pragma unroll 2
            for (int k = 0; k < 128; k++) {
                float4 wp = s_w1p[k];
                float bb = s_b1[k];
                unsigned long long vv[4];
                #pragma unroll
                for (int r = 0; r < 4; r++) {
                    float z = fmaf(wt[r].x, wp.x, fmaf(wt[r].y, wp.y,
                              fmaf(wt[r].z, wp.z, fmaf(wt[r].w, wp.w, bb))));
                    float v = fmaxf(z, 0.0f);
                    asm("mov.b64 %0, {%1, %1};" : "=l"(vv[r]) : "f"(v));
                }
                const ulonglong2* row = (const ulonglong2*)s_M4 + k * 16 + c * 4;
                #pragma unroll
                for (int t = 0; t < 4; t++) {
                    ulonglong2 m = row[t];
                    #pragma unroll
                    for (int r = 0; r < 4; r++) {
                        acc[r][2 * t]     = ffma2(m.x, vv[r], acc[r][2 * t]);
                        acc[r][2 * t + 1] = ffma2(m.y, vv[r], acc[r][2 * t + 1]);
                    }
                }
            }

            #pragma unroll
            for (int p = 0; p < 8; p++) {
                const int j = c * 16 + 2 * p;
                const float q0 = s_q[j], q1 = s_q[j + 1];
                const float e0 = s_e[j], e1 = s_e[j + 1];
                #pragma unroll
                for (int r = 0; r < 4; r++) {
                    float z0 = __uint_as_float((unsigned)(acc[r][p] & 0xFFFFFFFFull)) + q0;
                    float z1 = __uint_as_float((unsigned)(acc[r][p] >> 32))           + q1;
                    dec[r] = fmaf(e0, fmaxf(z0, 0.0f), dec[r]);
                    dec[r] = fmaf(e1, fmaxf(z1, 0.0f), dec[r]);
                }
            }
        }

        // ---- per r-set: cls write + rare argmax-gather overwrite ----
        #pragma unroll
        for (int r = 0; r < 4; r++) {
            const bool cls1 = valid[r] && (dec[r] > LN3);
            const long long rbase = base + 32 * r;
            unsigned mbits = __ballot_sync(FULL, cls1);
            while (mbits) {
                const int rr = __ffs(mbits) - 1;
                mbits &= mbits - 1;
                const long long b = rbase + rr;
                const int gmi = __shfl_sync(FULL, mmi[r], rr);
                const float4* gsrc = (const float4*)(x + b * 1024 + (size_t)gmi * 256);
                float4 v0 = gsrc[lane], v1 = gsrc[32 + lane];
                float4* orow = (float4*)(out + (size_t)b * 256);
                orow[lane]      = v0;
                orow[32 + lane] = v1;
            }
            if (write_cls && valid[r])
                out[(size_t)B * 260 + rbase + lane] = cls1 ? 1.0f : 0.0f;
        }
    }
}

extern "C" void kernel_launch(void* const* d_in, const int* in_sizes, int n_in,
                              void* d_out, int out_size)
{
    const float* x      = (const float*)d_in[0];
    const float* mask   = (const float*)d_in[1];
    const float* attn_w = (const float*)d_in[2];
    const float* attn_b = (const float*)d_in[3];
    const float* w1     = (const float*)d_in[4];
    const float* b1     = (const float*)d_in[5];
    const float* g1     = (const float*)d_in[6];
    const float* be1    = (const float*)d_in[7];
    const float* m1     = (const float*)d_in[8];
    const float* v1     = (const float*)d_in[9];
    const float* w2     = (const float*)d_in[10];
    const float* b2     = (const float*)d_in[11];
    const float* g2     = (const float*)d_in[12];
    const float* be2    = (const float*)d_in[13];
    const float* m2     = (const float*)d_in[14];
    const float* v2     = (const float*)d_in[15];
    const float* w3     = (const float*)d_in[16];
    const float* b3     = (const float*)d_in[17];
    float* out = (float*)d_out;

    const int B = in_sizes[0] / 1024;   // x = [B,4,256]
    const long long need_w = (long long)B * 260;
    const long long need_c = (long long)B * 261;
    const int write_weight = ((long long)out_size >= need_w) ? 1 : 0;
    const int write_cls    = ((long long)out_size >= need_c) ? 1 : 0;

    stream_kernel<<<2048, 256>>>(x, mask, attn_w, attn_b, out, B, write_weight);
    mlp_kernel<<<592, 128>>>(x, w1, b1, g1, be1, m1, v1,
                             w2, b2, g2, be2, m2, v2, w3, b3,
                             out, B, write_cls);
}

// round 9
// speedup vs baseline: 1.2963x; 1.0049x over previous
#include <cuda_runtime.h>
#include <cuda_bf16.h>

#define EPS 1e-5f
#define LN3 1.0986122886681098f

// ---- static scratch ----
__device__ __align__(16) float4 g_wt[1 << 19];   // per-row softmax weights
__device__ int g_flag[4096];                     // per-256-row-chunk ready flags

__device__ __forceinline__ float tanh_approx(float v) {
    float r;
    asm("tanh.approx.f32 %0, %1;" : "=f"(r) : "f"(v));
    return r;
}

__device__ __forceinline__ unsigned long long ffma2(
    unsigned long long a, unsigned long long b, unsigned long long c)
{
    unsigned long long d;
    asm("fma.rn.f32x2 %0, %1, %2, %3;" : "=l"(d) : "l"(a), "l"(b), "l"(c));
    return d;
}

// One kernel, two roles. Per 37-block tile: 32 stream blocks + 5 mlp blocks.
__global__ __launch_bounds__(256, 2) void pc_kernel(
    const float* __restrict__ x, const float* __restrict__ mask,
    const float* __restrict__ attn_w, const float* __restrict__ attn_b,
    const float* __restrict__ w1, const float* __restrict__ b1,
    const float* __restrict__ g1, const float* __restrict__ be1,
    const float* __restrict__ m1, const float* __restrict__ v1,
    const float* __restrict__ w2, const float* __restrict__ b2,
    const float* __restrict__ g2, const float* __restrict__ be2,
    const float* __restrict__ m2, const float* __restrict__ v2,
    const float* __restrict__ w3, const float* __restrict__ b3,
    float* __restrict__ out, int B, int write_weight, int write_cls,
    int nStreamBlocks, int nTasks, int nMlpWarps)
{
    __shared__ float4 s_M4[128 * 16];   // 32KB (mlp role)
    __shared__ float4 s_w1p[128];
    __shared__ float  s_b1[128];
    __shared__ float  s_q[64], s_e[64], s_ct[64];
    __shared__ float  s_a1[128], s_c1[128];
    __shared__ float  s_C;
    __shared__ float4 s_aw[64];         // (stream role)
    __shared__ float  s_ab;

    const int tid  = threadIdx.x;
    const int lane = tid & 31;
    const int warp = tid >> 5;
    const unsigned FULL = 0xFFFFFFFFu;

    const int tile = blockIdx.x / 37;
    const int pos  = blockIdx.x % 37;

    if (pos < 32) {
        // ======================= STREAM ROLE =======================
        const int s = tile * 32 + pos;
        if (s >= nStreamBlocks) return;

        for (int i = tid; i < 64; i += 256) s_aw[i] = ((const float4*)attn_w)[i];
        if (tid == 0) s_ab = attn_b[0];
        __syncthreads();

        const float4 wa = s_aw[lane], wb = s_aw[32 + lane];
        const float ab = s_ab;
        const long long base = (long long)s * 256 + warp * 32;

        for (int r = 0; r < 32; r++) {
            const long long b = base + r;
            if (b >= B) break;
            const float4 mk = __ldg(((const float4*)mask) + b);
            const float4* xr = (const float4*)(x + b * 1024);
            float4 xa0 = xr[lane],       xb0 = xr[32 + lane];
            float4 xa1 = xr[64 + lane],  xb1 = xr[96 + lane];
            float4 xa2 = xr[128 + lane], xb2 = xr[160 + lane];
            float4 xa3 = xr[192 + lane], xb3 = xr[224 + lane];

            float s0 = xa0.x*wa.x + xa0.y*wa.y + xa0.z*wa.z + xa0.w*wa.w
                     + xb0.x*wb.x + xb0.y*wb.y + xb0.z*wb.z + xb0.w*wb.w;
            float s1 = xa1.x*wa.x + xa1.y*wa.y + xa1.z*wa.z + xa1.w*wa.w
                     + xb1.x*wb.x + xb1.y*wb.y + xb1.z*wb.z + xb1.w*wb.w;
            float s2 = xa2.x*wa.x + xa2.y*wa.y + xa2.z*wa.z + xa2.w*wa.w
                     + xb2.x*wb.x + xb2.y*wb.y + xb2.z*wb.z + xb2.w*wb.w;
            float s3 = xa3.x*wa.x + xa3.y*wa.y + xa3.z*wa.z + xa3.w*wa.w
                     + xb3.x*wb.x + xb3.y*wb.y + xb3.z*wb.z + xb3.w*wb.w;
            #pragma unroll
            for (int o = 16; o; o >>= 1) {
                s0 += __shfl_xor_sync(FULL, s0, o);
                s1 += __shfl_xor_sync(FULL, s1, o);
                s2 += __shfl_xor_sync(FULL, s2, o);
                s3 += __shfl_xor_sync(FULL, s3, o);
            }

            float t0 = tanh_approx(s0 + ab) + mk.x;
            float t1 = tanh_approx(s1 + ab) + mk.y;
            float t2 = tanh_approx(s2 + ab) + mk.z;
            float t3 = tanh_approx(s3 + ab) + mk.w;

            float mx = fmaxf(fmaxf(t0, t1), fmaxf(t2, t3));
            float e0 = __expf(t0 - mx), e1 = __expf(t1 - mx);
            float e2 = __expf(t2 - mx), e3 = __expf(t3 - mx);
            float inv = 1.0f / (e0 + e1 + e2 + e3);
            float wt0 = e0 * inv, wt1 = e1 * inv, wt2 = e2 * inv, wt3 = e3 * inv;

            float4 pa, pb;
            pa.x = wt0*xa0.x + wt1*xa1.x + wt2*xa2.x + wt3*xa3.x;
            pa.y = wt0*xa0.y + wt1*xa1.y + wt2*xa2.y + wt3*xa3.y;
            pa.z = wt0*xa0.z + wt1*xa1.z + wt2*xa2.z + wt3*xa3.z;
            pa.w = wt0*xa0.w + wt1*xa1.w + wt2*xa2.w + wt3*xa3.w;
            pb.x = wt0*xb0.x + wt1*xb1.x + wt2*xb2.x + wt3*xb3.x;
            pb.y = wt0*xb0.y + wt1*xb1.y + wt2*xb2.y + wt3*xb3.y;
            pb.z = wt0*xb0.z + wt1*xb1.z + wt2*xb2.z + wt3*xb3.z;
            pb.w = wt0*xb0.w + wt1*xb1.w + wt2*xb2.w + wt3*xb3.w;

            float4* orow = (float4*)(out + (size_t)b * 256);
            orow[lane]      = pa;
            orow[32 + lane] = pb;

            if (lane == 0) {
                float4 wv = make_float4(wt0, wt1, wt2, wt3);
                g_wt[b] = wv;
                if (write_weight)
                    *(float4*)(out + (size_t)B * 256 + (size_t)b * 4) = wv;
            }
        }
        __syncthreads();             // all 256 rows of this chunk written
        if (tid == 0) {
            __threadfence();         // release
            atomicExch(&g_flag[s], 1);
        }
        return;
    }

    // ======================= MLP ROLE =======================
    const int mb = tile * 5 + (pos - 32);

    // ---- fold all classifier constants in-block ----
    for (int i = tid; i < 128; i += 256) {
        float a = g1[i] * rsqrtf(v1[i] + EPS);
        s_a1[i] = a; s_c1[i] = be1[i] - a * m1[i]; s_b1[i] = b1[i];
        s_w1p[i] = make_float4(w1[i*4], w1[i*4+1], w1[i*4+2], w1[i*4+3]);
    }
    __syncthreads();
    float* s_M = (float*)s_M4;
    for (int i = tid; i < 8192; i += 256) {
        int j = i >> 7, k = i & 127;
        s_M[k * 64 + j] = w2[j * 128 + k] * s_a1[k];
    }
    if (tid < 64) {
        float acc = b2[tid];
        #pragma unroll 8
        for (int k = 0; k < 128; k++) acc += w2[tid * 128 + k] * s_c1[k];
        s_q[tid] = acc;
        float a2 = g2[tid] * rsqrtf(v2[tid] + EPS);
        float wd = w3[64 + tid] - w3[tid];
        s_e[tid] = wd * a2;
        s_ct[tid] = wd * (be2[tid] - a2 * m2[tid]);
    }
    __syncthreads();
    if (tid == 0) {
        float C = b3[1] - b3[0];
        #pragma unroll 8
        for (int j = 0; j < 64; j++) C += s_ct[j];
        s_C = C;
    }
    __syncthreads();

    const float Cc = s_C;
    const int mwarp = mb * 8 + warp;

    for (int t = mwarp; t < nTasks; t += nMlpWarps) {
        // ---- wait for producer chunk (lane 0 polls, then fence all) ----
        if (lane == 0) {
            while (atomicAdd(&g_flag[t >> 1], 0) == 0) __nanosleep(128);
        }
        __syncwarp();
        __threadfence();             // acquire

        const long long base = (long long)t << 7;   // 128 rows per task

        bool  valid[4];
        float4 wt[4];
        #pragma unroll
        for (int r = 0; r < 4; r++) {
            long long row = base + 32 * r + lane;
            valid[r] = (row < B);
            wt[r] = valid[r] ? g_wt[row] : make_float4(1.f, 0.f, 0.f, 0.f);
        }

        float dec[4] = {Cc, Cc, Cc, Cc};

        #pragma unroll
        for (int c = 0; c < 4; c++) {         // j-chunks of 16 outputs
            unsigned long long acc[4][8];
            #pragma unroll
            for (int r = 0; r < 4; r++)
                #pragma unroll
                for (int p = 0; p < 8; p++) acc[r][p] = 0ull;

            #pragma unroll 2
            for (int k = 0; k < 128; k++) {
                float4 wp = s_w1p[k];
                float bb = s_b1[k];
                unsigned long long vv[4];
                #pragma unroll
                for (int r = 0; r < 4; r++) {
                    float z = fmaf(wt[r].x, wp.x, fmaf(wt[r].y, wp.y,
                              fmaf(wt[r].z, wp.z, fmaf(wt[r].w, wp.w, bb))));
                    float v = fmaxf(z, 0.0f);
                    asm("mov.b64 %0, {%1, %1};" : "=l"(vv[r]) : "f"(v));
                }
                const ulonglong2* row = (const ulonglong2*)s_M4 + k * 16 + c * 4;
                #pragma unroll
                for (int tt = 0; tt < 4; tt++) {
                    ulonglong2 m = row[tt];
                    #pragma unroll
                    for (int r = 0; r < 4; r++) {
                        acc[r][2 * tt]     = ffma2(m.x, vv[r], acc[r][2 * tt]);
                        acc[r][2 * tt + 1] = ffma2(m.y, vv[r], acc[r][2 * tt + 1]);
                    }
                }
            }
            #pragma unroll
            for (int p = 0; p < 8; p++) {
                const int j = c * 16 + 2 * p;
                const float q0 = s_q[j], q1 = s_q[j + 1];
                const float e0 = s_e[j], e1 = s_e[j + 1];
                #pragma unroll
                for (int r = 0; r < 4; r++) {
                    float z0 = __uint_as_float((unsigned)(acc[r][p] & 0xFFFFFFFFull)) + q0;
                    float z1 = __uint_as_float((unsigned)(acc[r][p] >> 32))           + q1;
                    dec[r] = fmaf(e0, fmaxf(z0, 0.0f), dec[r]);
                    dec[r] = fmaf(e1, fmaxf(z1, 0.0f), dec[r]);
                }
            }
        }

        // ---- per r-set: cls write + rare argmax-gather overwrite ----
        #pragma unroll
        for (int r = 0; r < 4; r++) {
            int mi = 0; float bm = wt[r].x;
            if (wt[r].y > bm) { bm = wt[r].y; mi = 1; }
            if (wt[r].z > bm) { bm = wt[r].z; mi = 2; }
            if (wt[r].w > bm) { bm = wt[r].w; mi = 3; }

            const bool cls1 = valid[r] && (dec[r] > LN3);
            const long long rbase = base + 32 * r;
            unsigned mbits = __ballot_sync(FULL, cls1);
            while (mbits) {
                const int rr = __ffs(mbits) - 1;
                mbits &= mbits - 1;
                const long long b = rbase + rr;
                const int gmi = __shfl_sync(FULL, mi, rr);
                const float4* gsrc = (const float4*)(x + b * 1024 + (size_t)gmi * 256);
                float4 v0 = gsrc[lane], v1 = gsrc[32 + lane];
                float4* orow = (float4*)(out + (size_t)b * 256);
                orow[lane]      = v0;
                orow[32 + lane] = v1;
            }
            if (write_cls && valid[r])
                out[(size_t)B * 260 + rbase + lane] = cls1 ? 1.0f : 0.0f;
        }
    }
}

extern "C" void kernel_launch(void* const* d_in, const int* in_sizes, int n_in,
                              void* d_out, int out_size)
{
    const float* x      = (const float*)d_in[0];
    const float* mask   = (const float*)d_in[1];
    const float* attn_w = (const float*)d_in[2];
    const float* attn_b = (const float*)d_in[3];
    const float* w1     = (const float*)d_in[4];
    const float* b1     = (const float*)d_in[5];
    const float* g1     = (const float*)d_in[6];
    const float* be1    = (const float*)d_in[7];
    const float* m1     = (const float*)d_in[8];
    const float* v1     = (const float*)d_in[9];
    const float* w2     = (const float*)d_in[10];
    const float* b2     = (const float*)d_in[11];
    const float* g2     = (const float*)d_in[12];
    const float* be2    = (const float*)d_in[13];
    const float* m2     = (const float*)d_in[14];
    const float* v2     = (const float*)d_in[15];
    const float* w3     = (const float*)d_in[16];
    const float* b3     = (const float*)d_in[17];
    float* out = (float*)d_out;

    const int B = in_sizes[0] / 1024;   // x = [B,4,256]
    const long long need_w = (long long)B * 260;
    const long long need_c = (long long)B * 261;
    const int write_weight = ((long long)out_size >= need_w) ? 1 : 0;
    const int write_cls    = ((long long)out_size >= need_c) ? 1 : 0;

    const int nStreamBlocks = (B + 255) >> 8;       // 256-row chunks
    const int nTasks        = (B + 127) >> 7;       // 128-row mlp tasks
    const int tiles         = (nStreamBlocks + 31) >> 5;
    const int grid          = tiles * 37;           // 32 stream + 5 mlp per tile
    const int nMlpWarps     = tiles * 5 * 8;

    void* flagPtr = nullptr;
    cudaGetSymbolAddress(&flagPtr, g_flag);
    cudaMemsetAsync(flagPtr, 0, sizeof(int) * 4096);

    pc_kernel<<<grid, 256>>>(x, mask, attn_w, attn_b,
                             w1, b1, g1, be1, m1, v1,
                             w2, b2, g2, be2, m2, v2, w3, b3,
                             out, B, write_weight, write_cls,
                             nStreamBlocks, nTasks, nMlpWarps);
}

// round 10
// speedup vs baseline: 1.3759x; 1.0613x over previous
#include <cuda_runtime.h>
#include <cuda_bf16.h>

#define EPS 1e-5f
#define LN3 1.0986122886681098f

// ---- static scratch ----
__device__ __align__(16) float4 g_wt[1 << 19];   // per-row softmax weights
__device__ int g_flag[4096];                     // per-256-row-chunk ready flags

__device__ __forceinline__ float tanh_approx(float v) {
    float r;
    asm("tanh.approx.f32 %0, %1;" : "=f"(r) : "f"(v));
    return r;
}

__device__ __forceinline__ unsigned long long ffma2(
    unsigned long long a, unsigned long long b, unsigned long long c)
{
    unsigned long long d;
    asm("fma.rn.f32x2 %0, %1, %2, %3;" : "=l"(d) : "l"(a), "l"(b), "l"(c));
    return d;
}

// One kernel, two roles. Per 40-block tile: 32 stream + 8 mlp blocks.
__global__ __launch_bounds__(256, 2) void pc_kernel(
    const float* __restrict__ x, const float* __restrict__ mask,
    const float* __restrict__ attn_w, const float* __restrict__ attn_b,
    const float* __restrict__ w1, const float* __restrict__ b1,
    const float* __restrict__ g1, const float* __restrict__ be1,
    const float* __restrict__ m1, const float* __restrict__ v1,
    const float* __restrict__ w2, const float* __restrict__ b2,
    const float* __restrict__ g2, const float* __restrict__ be2,
    const float* __restrict__ m2, const float* __restrict__ v2,
    const float* __restrict__ w3, const float* __restrict__ b3,
    float* __restrict__ out, int B, int write_weight, int write_cls,
    int nStreamBlocks, int nTasks, int nMlpWarps)
{
    __shared__ float4 s_M4[128 * 16];   // 32KB (mlp role)
    __shared__ float4 s_w1p[128];
    __shared__ float  s_b1[128];
    __shared__ float  s_q[64], s_e[64], s_ct[64];
    __shared__ float  s_a1[128], s_c1[128];
    __shared__ float  s_C;
    __shared__ float4 s_aw[64];         // (stream role)
    __shared__ float  s_ab;

    const int tid  = threadIdx.x;
    const int lane = tid & 31;
    const int warp = tid >> 5;
    const unsigned FULL = 0xFFFFFFFFu;

    const int tile = blockIdx.x / 40;
    const int pos  = blockIdx.x % 40;

    if (pos < 32) {
        // ======================= STREAM ROLE (dual-row) =======================
        const int s = tile * 32 + pos;
        if (s >= nStreamBlocks) return;

        for (int i = tid; i < 64; i += 256) s_aw[i] = ((const float4*)attn_w)[i];
        if (tid == 0) s_ab = attn_b[0];
        __syncthreads();

        const float4 wa = s_aw[lane], wb = s_aw[32 + lane];
        const float ab = s_ab;
        const long long base = (long long)s * 256 + warp * 32;

        for (int r = 0; r < 32; r += 2) {
            const long long b0 = base + r;
            const long long b1r = b0 + 1;
            if (b0 >= B) break;
            const bool has2 = (b1r < B);

            const float4 mk0 = __ldg(((const float4*)mask) + b0);
            const float4 mk1 = has2 ? __ldg(((const float4*)mask) + b1r) : mk0;

            const float4* xr0 = (const float4*)(x + b0 * 1024);
            const float4* xr1 = (const float4*)(x + (has2 ? b1r : b0) * 1024);

            // row 0: 8 loads; row 1: 8 loads -- 16 LDG.128 in flight per warp
            float4 Aa0 = xr0[lane],       Ab0 = xr0[32 + lane];
            float4 Aa1 = xr0[64 + lane],  Ab1 = xr0[96 + lane];
            float4 Aa2 = xr0[128 + lane], Ab2 = xr0[160 + lane];
            float4 Aa3 = xr0[192 + lane], Ab3 = xr0[224 + lane];
            float4 Ba0 = xr1[lane],       Bb0 = xr1[32 + lane];
            float4 Ba1 = xr1[64 + lane],  Bb1 = xr1[96 + lane];
            float4 Ba2 = xr1[128 + lane], Bb2 = xr1[160 + lane];
            float4 Ba3 = xr1[192 + lane], Bb3 = xr1[224 + lane];

            float u0 = Aa0.x*wa.x + Aa0.y*wa.y + Aa0.z*wa.z + Aa0.w*wa.w
                     + Ab0.x*wb.x + Ab0.y*wb.y + Ab0.z*wb.z + Ab0.w*wb.w;
            float u1 = Aa1.x*wa.x + Aa1.y*wa.y + Aa1.z*wa.z + Aa1.w*wa.w
                     + Ab1.x*wb.x + Ab1.y*wb.y + Ab1.z*wb.z + Ab1.w*wb.w;
            float u2 = Aa2.x*wa.x + Aa2.y*wa.y + Aa2.z*wa.z + Aa2.w*wa.w
                     + Ab2.x*wb.x + Ab2.y*wb.y + Ab2.z*wb.z + Ab2.w*wb.w;
            float u3 = Aa3.x*wa.x + Aa3.y*wa.y + Aa3.z*wa.z + Aa3.w*wa.w
                     + Ab3.x*wb.x + Ab3.y*wb.y + Ab3.z*wb.z + Ab3.w*wb.w;
            float v0 = Ba0.x*wa.x + Ba0.y*wa.y + Ba0.z*wa.z + Ba0.w*wa.w
                     + Bb0.x*wb.x + Bb0.y*wb.y + Bb0.z*wb.z + Bb0.w*wb.w;
            float v1 = Ba1.x*wa.x + Ba1.y*wa.y + Ba1.z*wa.z + Ba1.w*wa.w
                     + Bb1.x*wb.x + Bb1.y*wb.y + Bb1.z*wb.z + Bb1.w*wb.w;
            float v2 = Ba2.x*wa.x + Ba2.y*wa.y + Ba2.z*wa.z + Ba2.w*wa.w
                     + Bb2.x*wb.x + Bb2.y*wb.y + Bb2.z*wb.z + Bb2.w*wb.w;
            float v3 = Ba3.x*wa.x + Ba3.y*wa.y + Ba3.z*wa.z + Ba3.w*wa.w
                     + Bb3.x*wb.x + Bb3.y*wb.y + Bb3.z*wb.z + Bb3.w*wb.w;
            #pragma unroll
            for (int o = 16; o; o >>= 1) {
                u0 += __shfl_xor_sync(FULL, u0, o);
                u1 += __shfl_xor_sync(FULL, u1, o);
                u2 += __shfl_xor_sync(FULL, u2, o);
                u3 += __shfl_xor_sync(FULL, u3, o);
                v0 += __shfl_xor_sync(FULL, v0, o);
                v1 += __shfl_xor_sync(FULL, v1, o);
                v2 += __shfl_xor_sync(FULL, v2, o);
                v3 += __shfl_xor_sync(FULL, v3, o);
            }

            float t0 = tanh_approx(u0 + ab) + mk0.x;
            float t1 = tanh_approx(u1 + ab) + mk0.y;
            float t2 = tanh_approx(u2 + ab) + mk0.z;
            float t3 = tanh_approx(u3 + ab) + mk0.w;
            float p0 = tanh_approx(v0 + ab) + mk1.x;
            float p1 = tanh_approx(v1 + ab) + mk1.y;
            float p2 = tanh_approx(v2 + ab) + mk1.z;
            float p3 = tanh_approx(v3 + ab) + mk1.w;

            float mxA = fmaxf(fmaxf(t0, t1), fmaxf(t2, t3));
            float eA0 = __expf(t0 - mxA), eA1 = __expf(t1 - mxA);
            float eA2 = __expf(t2 - mxA), eA3 = __expf(t3 - mxA);
            float invA = 1.0f / (eA0 + eA1 + eA2 + eA3);
            float wA0 = eA0 * invA, wA1 = eA1 * invA, wA2 = eA2 * invA, wA3 = eA3 * invA;

            float mxB = fmaxf(fmaxf(p0, p1), fmaxf(p2, p3));
            float eB0 = __expf(p0 - mxB), eB1 = __expf(p1 - mxB);
            float eB2 = __expf(p2 - mxB), eB3 = __expf(p3 - mxB);
            float invB = 1.0f / (eB0 + eB1 + eB2 + eB3);
            float wB0 = eB0 * invB, wB1 = eB1 * invB, wB2 = eB2 * invB, wB3 = eB3 * invB;

            float4 oa, ob;
            oa.x = wA0*Aa0.x + wA1*Aa1.x + wA2*Aa2.x + wA3*Aa3.x;
            oa.y = wA0*Aa0.y + wA1*Aa1.y + wA2*Aa2.y + wA3*Aa3.y;
            oa.z = wA0*Aa0.z + wA1*Aa1.z + wA2*Aa2.z + wA3*Aa3.z;
            oa.w = wA0*Aa0.w + wA1*Aa1.w + wA2*Aa2.w + wA3*Aa3.w;
            ob.x = wA0*Ab0.x + wA1*Ab1.x + wA2*Ab2.x + wA3*Ab3.x;
            ob.y = wA0*Ab0.y + wA1*Ab1.y + wA2*Ab2.y + wA3*Ab3.y;
            ob.z = wA0*Ab0.z + wA1*Ab1.z + wA2*Ab2.z + wA3*Ab3.z;
            ob.w = wA0*Ab0.w + wA1*Ab1.w + wA2*Ab2.w + wA3*Ab3.w;
            float4* orow0 = (float4*)(out + (size_t)b0 * 256);
            orow0[lane]      = oa;
            orow0[32 + lane] = ob;

            if (has2) {
                float4 pa, pb;
                pa.x = wB0*Ba0.x + wB1*Ba1.x + wB2*Ba2.x + wB3*Ba3.x;
                pa.y = wB0*Ba0.y + wB1*Ba1.y + wB2*Ba2.y + wB3*Ba3.y;
                pa.z = wB0*Ba0.z + wB1*Ba1.z + wB2*Ba2.z + wB3*Ba3.z;
                pa.w = wB0*Ba0.w + wB1*Ba1.w + wB2*Ba2.w + wB3*Ba3.w;
                pb.x = wB0*Bb0.x + wB1*Bb1.x + wB2*Bb2.x + wB3*Bb3.x;
                pb.y = wB0*Bb0.y + wB1*Bb1.y + wB2*Bb2.y + wB3*Bb3.y;
                pb.z = wB0*Bb0.z + wB1*Bb1.z + wB2*Bb2.z + wB3*Bb3.z;
                pb.w = wB0*Bb0.w + wB1*Bb1.w + wB2*Bb2.w + wB3*Bb3.w;
                float4* orow1 = (float4*)(out + (size_t)b1r * 256);
                orow1[lane]      = pa;
                orow1[32 + lane] = pb;
            }

            if (lane == 0) {
                float4 wv0 = make_float4(wA0, wA1, wA2, wA3);
                g_wt[b0] = wv0;
                if (write_weight)
                    *(float4*)(out + (size_t)B * 256 + (size_t)b0 * 4) = wv0;
                if (has2) {
                    float4 wv1 = make_float4(wB0, wB1, wB2, wB3);
                    g_wt[b1r] = wv1;
                    if (write_weight)
                        *(float4*)(out + (size_t)B * 256 + (size_t)b1r * 4) = wv1;
                }
            }
        }
        __syncthreads();             // all 256 rows of this chunk written
        if (tid == 0) {
            __threadfence();         // release
            atomicExch(&g_flag[s], 1);
        }
        return;
    }

    // ======================= MLP ROLE (R=2 rows/lane, C=4 j-chunks) =======================
    const int mb = tile * 8 + (pos - 32);

    // ---- fold all classifier constants in-block ----
    for (int i = tid; i < 128; i += 256) {
        float a = g1[i] * rsqrtf(v1[i] + EPS);
        s_a1[i] = a; s_c1[i] = be1[i] - a * m1[i]; s_b1[i] = b1[i];
        s_w1p[i] = make_float4(w1[i*4], w1[i*4+1], w1[i*4+2], w1[i*4+3]);
    }
    __syncthreads();
    float* s_M = (float*)s_M4;
    for (int i = tid; i < 8192; i += 256) {
        int j = i >> 7, k = i & 127;
        s_M[k * 64 + j] = w2[j * 128 + k] * s_a1[k];
    }
    if (tid < 64) {
        float acc = b2[tid];
        #pragma unroll 8
        for (int k = 0; k < 128; k++) acc += w2[tid * 128 + k] * s_c1[k];
        s_q[tid] = acc;
        float a2 = g2[tid] * rsqrtf(v2[tid] + EPS);
        float wd = w3[64 + tid] - w3[tid];
        s_e[tid] = wd * a2;
        s_ct[tid] = wd * (be2[tid] - a2 * m2[tid]);
    }
    __syncthreads();
    if (tid == 0) {
        float C = b3[1] - b3[0];
        #pragma unroll 8
        for (int j = 0; j < 64; j++) C += s_ct[j];
        s_C = C;
    }
    __syncthreads();

    const float Cc = s_C;
    const int mwarp = mb * 8 + warp;

    for (int t = mwarp; t < nTasks; t += nMlpWarps) {
        // ---- wait for producer chunk (task = 64 rows; chunk = 256 rows) ----
        if (lane == 0) {
            while (atomicAdd(&g_flag[t >> 2], 0) == 0) __nanosleep(128);
        }
        __syncwarp();
        __threadfence();             // acquire

        const long long base = (long long)t << 6;   // 64 rows per task

        bool  valid[2];
        float4 wt[2];
        #pragma unroll
        for (int r = 0; r < 2; r++) {
            long long row = base + 32 * r + lane;
            valid[r] = (row < B);
            wt[r] = valid[r] ? g_wt[row] : make_float4(1.f, 0.f, 0.f, 0.f);
        }

        float dec[2] = {Cc, Cc};

        #pragma unroll
        for (int c = 0; c < 4; c++) {         // j-chunks of 16 outputs
            unsigned long long acc[2][8];
            #pragma unroll
            for (int r = 0; r < 2; r++)
                #pragma unroll
                for (int p = 0; p < 8; p++) acc[r][p] = 0ull;

            #pragma unroll 2
            for (int k = 0; k < 128; k++) {
                float4 wp = s_w1p[k];
                float bb = s_b1[k];
                unsigned long long vv[2];
                #pragma unroll
                for (int r = 0; r < 2; r++) {
                    float z = fmaf(wt[r].x, wp.x, fmaf(wt[r].y, wp.y,
                              fmaf(wt[r].z, wp.z, fmaf(wt[r].w, wp.w, bb))));
                    float v = fmaxf(z, 0.0f);
                    asm("mov.b64 %0, {%1, %1};" : "=l"(vv[r]) : "f"(v));
                }
                const ulonglong2* row = (const ulonglong2*)s_M4 + k * 16 + c * 4;
                #pragma unroll
                for (int tt = 0; tt < 4; tt++) {
                    ulonglong2 m = row[tt];
                    #pragma unroll
                    for (int r = 0; r < 2; r++) {
                        acc[r][2 * tt]     = ffma2(m.x, vv[r], acc[r][2 * tt]);
                        acc[r][2 * tt + 1] = ffma2(m.y, vv[r], acc[r][2 * tt + 1]);
                    }
                }
            }
            #pragma unroll
            for (int p = 0; p < 8; p++) {
                const int j = c * 16 + 2 * p;
                const float q0 = s_q[j], q1 = s_q[j + 1];
                const float e0 = s_e[j], e1 = s_e[j + 1];
                #pragma unroll
                for (int r = 0; r < 2; r++) {
                    float z0 = __uint_as_float((unsigned)(acc[r][p] & 0xFFFFFFFFull)) + q0;
                    float z1 = __uint_as_float((unsigned)(acc[r][p] >> 32))           + q1;
                    dec[r] = fmaf(e0, fmaxf(z0, 0.0f), dec[r]);
                    dec[r] = fmaf(e1, fmaxf(z1, 0.0f), dec[r]);
                }
            }
        }

        // ---- per r-set: cls write + rare argmax-gather overwrite ----
        #pragma unroll
        for (int r = 0; r < 2; r++) {
            int mi = 0; float bm = wt[r].x;
            if (wt[r].y > bm) { bm = wt[r].y; mi = 1; }
            if (wt[r].z > bm) { bm = wt[r].z; mi = 2; }
            if (wt[r].w > bm) { bm = wt[r].w; mi = 3; }

            const bool cls1 = valid[r] && (dec[r] > LN3);
            const long long rbase = base + 32 * r;
            unsigned mbits = __ballot_sync(FULL, cls1);
            while (mbits) {
                const int rr = __ffs(mbits) - 1;
                mbits &= mbits - 1;
                const long long b = rbase + rr;
                const int gmi = __shfl_sync(FULL, mi, rr);
                const float4* gsrc = (const float4*)(x + b * 1024 + (size_t)gmi * 256);
                float4 v0 = gsrc[lane], v1 = gsrc[32 + lane];
                float4* orow = (float4*)(out + (size_t)b * 256);
                orow[lane]      = v0;
                orow[32 + lane] = v1;
            }
            if (write_cls && valid[r])
                out[(size_t)B * 260 + rbase + lane] = cls1 ? 1.0f : 0.0f;
        }
    }
}

extern "C" void kernel_launch(void* const* d_in, const int* in_sizes, int n_in,
                              void* d_out, int out_size)
{
    const float* x      = (const float*)d_in[0];
    const float* mask   = (const float*)d_in[1];
    const float* attn_w = (const float*)d_in[2];
    const float* attn_b = (const float*)d_in[3];
    const float* w1     = (const float*)d_in[4];
    const float* b1     = (const float*)d_in[5];
    const float* g1     = (const float*)d_in[6];
    const float* be1    = (const float*)d_in[7];
    const float* m1     = (const float*)d_in[8];
    const float* v1     = (const float*)d_in[9];
    const float* w2     = (const float*)d_in[10];
    const float* b2     = (const float*)d_in[11];
    const float* g2     = (const float*)d_in[12];
    const float* be2    = (const float*)d_in[13];
    const float* m2     = (const float*)d_in[14];
    const float* v2     = (const float*)d_in[15];
    const float* w3     = (const float*)d_in[16];
    const float* b3     = (const float*)d_in[17];
    float* out = (float*)d_out;

    const int B = in_sizes[0] / 1024;   // x = [B,4,256]
    const long long need_w = (long long)B * 260;
    const long long need_c = (long long)B * 261;
    const int write_weight = ((long long)out_size >= need_w) ? 1 : 0;
    const int write_cls    = ((long long)out_size >= need_c) ? 1 : 0;

    const int nStreamBlocks = (B + 255) >> 8;       // 256-row chunks
    const int nTasks        = (B + 63) >> 6;        // 64-row mlp tasks
    const int tiles         = (nStreamBlocks + 31) >> 5;
    const int grid          = tiles * 40;           // 32 stream + 8 mlp per tile
    const int nMlpWarps     = tiles * 8 * 8;

    void* flagPtr = nullptr;
    cudaGetSymbolAddress(&flagPtr, g_flag);
    cudaMemsetAsync(flagPtr, 0, sizeof(int) * 4096);

    pc_kernel<<<grid, 256>>>(x, mask, attn_w, attn_b,
                             w1, b1, g1, be1, m1, v1,
                             w2, b2, g2, be2, m2, v2, w3, b3,
                             out, B, write_weight, write_cls,
                             nStreamBlocks, nTasks, nMlpWarps);
}